// round 1
// baseline (speedup 1.0000x reference)
#include <cuda_runtime.h>
#include <math.h>

// ---------------- problem constants ----------------
#define BSZ    2
#define CDIM   256
#define LIMG   4096          // H*W = 64*64
#define DI     512           // D_INNER
#define DS     16            // D_STATE
#define DR     16            // DT_RANK
#define NCHUNK 64
#define TCH    64            // NCHUNK*TCH = LIMG
#define MROWS  8192          // BSZ*LIMG

// ---------------- scratch (static device arrays; no allocation) ----------------
__device__ float g_t0 [MROWS * CDIM];        // after cv1 + LN   (8 MB)
__device__ float g_xz [MROWS * 2 * DI];      // in_proj output   (32 MB)
__device__ float g_u  [MROWS * DI];          // silu(conv)       (16 MB)
__device__ float g_dt [MROWS * DI];          // softplus dt      (16 MB)
__device__ float g_Bm [MROWS * DS];
__device__ float g_Cm [MROWS * DS];
__device__ float g_Hc [BSZ * DI * NCHUNK * DS];   // chunk-local states
__device__ float g_Dc [BSZ * DI * NCHUNK];        // chunk dt sums
__device__ float g_hs [BSZ * DI * NCHUNK * DS];   // chunk start states
__device__ float g_y  [MROWS * DI];          // gated scan output (16 MB)
__device__ float g_t2 [MROWS * CDIM];        // out_proj output   (8 MB)

// ================= generic NT SGEMM: C[m,n] = sum_k A[m,k] * W[n,k] (+bias)(+resid) ==============
// A_IMG:  A[m,k] lives at A[(b*K + k)*LIMG + (m % LIMG)]  (NCHW image, b = m / LIMG)
// OUT_IMG: write C to [(b*N + n)*LIMG + l] with optional residual of same layout
template<bool A_IMG, bool OUT_IMG>
__global__ void __launch_bounds__(256) gemm_nt(
    const float* __restrict__ A, const float* __restrict__ W,
    const float* __restrict__ bias, const float* __restrict__ resid,
    float* __restrict__ Cmat, int M, int N, int K)
{
    const int BM = 128, BN = 128, BK = 8;
    __shared__ float As[BK][BM];
    __shared__ float Bs[BK][BN];

    int t  = threadIdx.x;
    int tx = t & 15, ty = t >> 4;
    int m0 = blockIdx.y * BM;
    int n0 = blockIdx.x * BN;

    float acc[8][8];
#pragma unroll
    for (int i = 0; i < 8; i++)
#pragma unroll
        for (int j = 0; j < 8; j++) acc[i][j] = 0.f;

    for (int k0 = 0; k0 < K; k0 += BK) {
        if (A_IMG) {
            int b  = m0 / LIMG;
            int l0 = m0 % LIMG;            // BM divides LIMG: tile never crosses batch
            int k  = t >> 5;               // 0..7
            int m  = (t & 31) * 4;         // 0..124
            float4 v = *(const float4*)&A[(size_t)(b * K + k0 + k) * LIMG + l0 + m];
            *(float4*)&As[k][m] = v;
        } else {
            int m = t >> 1;
            int g = (t & 1) * 4;
            float4 v = *(const float4*)&A[(size_t)(m0 + m) * K + k0 + g];
            As[g + 0][m] = v.x; As[g + 1][m] = v.y; As[g + 2][m] = v.z; As[g + 3][m] = v.w;
        }
        {
            int n = t >> 1;
            int g = (t & 1) * 4;
            float4 v = *(const float4*)&W[(size_t)(n0 + n) * K + k0 + g];
            Bs[g + 0][n] = v.x; Bs[g + 1][n] = v.y; Bs[g + 2][n] = v.z; Bs[g + 3][n] = v.w;
        }
        __syncthreads();

#pragma unroll
        for (int kk = 0; kk < BK; kk++) {
            float a[8], bf[8];
#pragma unroll
            for (int i = 0; i < 8; i++) a[i]  = As[kk][ty * 8 + i];
#pragma unroll
            for (int j = 0; j < 8; j++) bf[j] = Bs[kk][tx * 8 + j];
#pragma unroll
            for (int i = 0; i < 8; i++)
#pragma unroll
                for (int j = 0; j < 8; j++) acc[i][j] += a[i] * bf[j];
        }
        __syncthreads();
    }

#pragma unroll
    for (int i = 0; i < 8; i++) {
        int m = m0 + ty * 8 + i;
#pragma unroll
        for (int j = 0; j < 8; j++) {
            int n = n0 + tx * 8 + j;
            float v = acc[i][j];
            if (bias) v += bias[n];
            if (OUT_IMG) {
                int b = m / LIMG, l = m % LIMG;
                size_t o = (size_t)(b * N + n) * LIMG + l;
                if (resid) v += resid[o];
                Cmat[o] = v;
            } else {
                Cmat[(size_t)m * N + n] = v;
            }
        }
    }
}

// ================= LayerNorm over C=256 per row =================
__global__ void __launch_bounds__(256) ln_kernel(
    float* __restrict__ t0, const float* __restrict__ gam, const float* __restrict__ bet)
{
    int m = blockIdx.x;
    int c = threadIdx.x;
    float v = t0[(size_t)m * CDIM + c];
    float s1 = v, s2 = v * v;
#pragma unroll
    for (int off = 16; off; off >>= 1) {
        s1 += __shfl_xor_sync(0xffffffffu, s1, off);
        s2 += __shfl_xor_sync(0xffffffffu, s2, off);
    }
    __shared__ float a1[8], a2[8], mv[2];
    int wid = c >> 5, lane = c & 31;
    if (lane == 0) { a1[wid] = s1; a2[wid] = s2; }
    __syncthreads();
    if (c == 0) {
        float x1 = 0.f, x2 = 0.f;
        for (int i = 0; i < 8; i++) { x1 += a1[i]; x2 += a2[i]; }
        float mu = x1 * (1.f / CDIM);
        mv[0] = mu;
        mv[1] = rsqrtf(x2 * (1.f / CDIM) - mu * mu + 1e-5f);
    }
    __syncthreads();
    t0[(size_t)m * CDIM + c] = (v - mv[0]) * mv[1] * gam[c] + bet[c];
}

// ================= depthwise causal conv (width 4) + SiLU =================
__global__ void __launch_bounds__(512) conv_silu_kernel(
    const float* __restrict__ xz, const float* __restrict__ cw,
    const float* __restrict__ cb, float* __restrict__ u)
{
    int l = blockIdx.x;
    int b = blockIdx.y;
    int d = threadIdx.x;
    float s = cb[d];
#pragma unroll
    for (int k = 0; k < 4; k++) {
        int ls = l - 3 + k;
        if (ls >= 0) s += cw[d * 4 + k] * xz[(size_t)(b * LIMG + ls) * (2 * DI) + d];
    }
    float sig = 1.f / (1.f + __expf(-s));
    u[(size_t)(b * LIMG + l) * DI + d] = s * sig;
}

// ================= x_proj (48x512) + dt_proj (512x16) + softplus, fused =================
#define XPROWS 16
__global__ void __launch_bounds__(256) xproj_dt_kernel(
    const float* __restrict__ u, const float* __restrict__ xpw,
    const float* __restrict__ dtw, const float* __restrict__ dtb,
    float* __restrict__ dtout, float* __restrict__ Bout, float* __restrict__ Cout)
{
    __shared__ float su[XPROWS][DI];
    __shared__ float xd[XPROWS][48];
    int m0 = blockIdx.x * XPROWS;
    int t  = threadIdx.x;

    for (int idx = t; idx < XPROWS * DI; idx += 256) {
        int r = idx >> 9, k = idx & 511;
        su[r][k] = u[(size_t)(m0 + r) * DI + k];
    }
    __syncthreads();

    int w = t >> 5, lane = t & 31;
#pragma unroll
    for (int rr = 0; rr < 2; rr++) {
        int row = w * 2 + rr;
        for (int j = 0; j < 48; j++) {
            float s = 0.f;
#pragma unroll
            for (int i = 0; i < 16; i++) {
                int k = lane + 32 * i;
                s += su[row][k] * xpw[(size_t)j * DI + k];
            }
#pragma unroll
            for (int off = 16; off; off >>= 1) s += __shfl_xor_sync(0xffffffffu, s, off);
            if (lane == 0) xd[row][j] = s;
        }
    }
    __syncthreads();

    for (int idx = t; idx < XPROWS * DI; idx += 256) {
        int r = idx >> 9, d = idx & 511;
        float s = dtb[d];
#pragma unroll
        for (int q = 0; q < DR; q++) s += dtw[d * DR + q] * xd[r][q];
        float sp = (s > 20.f) ? s : log1pf(expf(s));
        dtout[(size_t)(m0 + r) * DI + d] = sp;
    }
    for (int idx = t; idx < XPROWS * DS; idx += 256) {
        int r = idx >> 4, n = idx & 15;
        Bout[(m0 + r) * DS + n] = xd[r][DR + n];
        Cout[(m0 + r) * DS + n] = xd[r][DR + DS + n];
    }
}

// ================= selective scan, chunked (3 phases) =================
// warp owns (b, d, chunk); lanes 0..15 = states (lanes 16..31 duplicate for uniform shuffles)
__global__ void __launch_bounds__(256) scan_phase1(
    const float* __restrict__ dt, const float* __restrict__ u,
    const float* __restrict__ Bm, const float* __restrict__ A_log,
    float* __restrict__ Hc, float* __restrict__ Dc)
{
    int gw   = (blockIdx.x * 256 + threadIdx.x) >> 5;   // 0..65535
    int lane = threadIdx.x & 31;
    int n    = lane & 15;
    int c = gw & (NCHUNK - 1);
    int d = (gw >> 6) & (DI - 1);
    int b = gw >> 15;

    float An = -expf(A_log[d * DS + n]);
    float h = 0.f, S = 0.f;
    size_t base  = (size_t)(b * LIMG + c * TCH) * DI + d;
    size_t baseB = (size_t)(b * LIMG + c * TCH) * DS + n;
#pragma unroll 4
    for (int i = 0; i < TCH; i++) {
        float dtv = dt[base + (size_t)i * DI];
        float uv  = u [base + (size_t)i * DI];
        float Bv  = Bm[baseB + (size_t)i * DS];
        h = __expf(dtv * An) * h + dtv * Bv * uv;
        S += dtv;
    }
    if (lane < 16) {
        Hc[(size_t)gw * DS + n] = h;
        if (n == 0) Dc[gw] = S;
    }
}

__global__ void __launch_bounds__(256) scan_phase2(
    const float* __restrict__ Hc, const float* __restrict__ Dc,
    const float* __restrict__ A_log, float* __restrict__ hstart)
{
    int gw   = (blockIdx.x * 256 + threadIdx.x) >> 5;   // 0..1023 = b*DI + d
    int lane = threadIdx.x & 31;
    int n    = lane & 15;
    int d    = gw & (DI - 1);
    float An = -expf(A_log[d * DS + n]);
    float hs = 0.f;
    size_t bb = (size_t)gw * NCHUNK;
    for (int c = 0; c < NCHUNK; c++) {
        if (lane < 16) hstart[(bb + c) * DS + n] = hs;
        float Hv = Hc[(bb + c) * DS + n];
        float Dv = Dc[bb + c];
        hs = __expf(An * Dv) * hs + Hv;
    }
}

__global__ void __launch_bounds__(256) scan_phase3(
    const float* __restrict__ dt, const float* __restrict__ u,
    const float* __restrict__ Bm, const float* __restrict__ Cm,
    const float* __restrict__ A_log, const float* __restrict__ Dpar,
    const float* __restrict__ xz, const float* __restrict__ hstart,
    float* __restrict__ y)
{
    int gw   = (blockIdx.x * 256 + threadIdx.x) >> 5;
    int lane = threadIdx.x & 31;
    int n    = lane & 15;
    int c = gw & (NCHUNK - 1);
    int d = (gw >> 6) & (DI - 1);
    int b = gw >> 15;

    float An = -expf(A_log[d * DS + n]);
    float Dd = Dpar[d];
    float h  = hstart[(size_t)gw * DS + n];
    size_t base  = (size_t)(b * LIMG + c * TCH) * DI + d;
    size_t baseB = (size_t)(b * LIMG + c * TCH) * DS + n;
    size_t basez = (size_t)(b * LIMG + c * TCH) * (2 * DI) + DI + d;
#pragma unroll 2
    for (int i = 0; i < TCH; i++) {
        float dtv = dt[base + (size_t)i * DI];
        float uv  = u [base + (size_t)i * DI];
        float Bv  = Bm[baseB + (size_t)i * DS];
        float Cv  = Cm[baseB + (size_t)i * DS];
        h = __expf(dtv * An) * h + dtv * Bv * uv;
        float p = h * Cv;
        p += __shfl_xor_sync(0xffffffffu, p, 8);
        p += __shfl_xor_sync(0xffffffffu, p, 4);
        p += __shfl_xor_sync(0xffffffffu, p, 2);
        p += __shfl_xor_sync(0xffffffffu, p, 1);
        if (lane == 0) {
            float zv  = xz[basez + (size_t)i * (2 * DI)];
            float yy  = p + uv * Dd;
            float sig = 1.f / (1.f + __expf(-zv));
            y[base + (size_t)i * DI] = yy * (zv * sig);
        }
    }
}

// ================= launch =================
extern "C" void kernel_launch(void* const* d_in, const int* in_sizes, int n_in,
                              void* d_out, int out_size)
{
    (void)in_sizes; (void)n_in; (void)out_size;
    const float* x         = (const float*)d_in[0];
    const float* cv1_w     = (const float*)d_in[1];
    const float* cv1_b     = (const float*)d_in[2];
    const float* ln_g      = (const float*)d_in[3];
    const float* ln_b      = (const float*)d_in[4];
    const float* in_proj_w = (const float*)d_in[5];
    const float* conv_w    = (const float*)d_in[6];
    const float* conv_b    = (const float*)d_in[7];
    const float* x_proj_w  = (const float*)d_in[8];
    const float* dt_proj_w = (const float*)d_in[9];
    const float* dt_proj_b = (const float*)d_in[10];
    const float* A_log     = (const float*)d_in[11];
    const float* Dp        = (const float*)d_in[12];
    const float* out_proj_w= (const float*)d_in[13];
    const float* cv2_w     = (const float*)d_in[14];
    const float* cv2_b     = (const float*)d_in[15];
    float* out = (float*)d_out;

    float *t0, *xz, *u, *dt, *Bm, *Cm, *Hc, *Dc, *hs, *y, *t2;
    cudaGetSymbolAddress((void**)&t0, g_t0);
    cudaGetSymbolAddress((void**)&xz, g_xz);
    cudaGetSymbolAddress((void**)&u,  g_u);
    cudaGetSymbolAddress((void**)&dt, g_dt);
    cudaGetSymbolAddress((void**)&Bm, g_Bm);
    cudaGetSymbolAddress((void**)&Cm, g_Cm);
    cudaGetSymbolAddress((void**)&Hc, g_Hc);
    cudaGetSymbolAddress((void**)&Dc, g_Dc);
    cudaGetSymbolAddress((void**)&hs, g_hs);
    cudaGetSymbolAddress((void**)&y,  g_y);
    cudaGetSymbolAddress((void**)&t2, g_t2);

    // 1) cv1 (1x1 conv as GEMM from NCHW) -> t0 rows (b*L, C)
    gemm_nt<true,  false><<<dim3(CDIM / 128, MROWS / 128), 256>>>(
        x, cv1_w, cv1_b, nullptr, t0, MROWS, CDIM, CDIM);
    // 2) LayerNorm in-place on t0
    ln_kernel<<<MROWS, 256>>>(t0, ln_g, ln_b);
    // 3) in_proj -> xz (b*L, 1024)
    gemm_nt<false, false><<<dim3((2 * DI) / 128, MROWS / 128), 256>>>(
        t0, in_proj_w, nullptr, nullptr, xz, MROWS, 2 * DI, CDIM);
    // 4) depthwise causal conv + SiLU -> u
    conv_silu_kernel<<<dim3(LIMG, BSZ), 512>>>(xz, conv_w, conv_b, u);
    // 5) x_proj + dt_proj + softplus -> dt, B, C
    xproj_dt_kernel<<<MROWS / XPROWS, 256>>>(u, x_proj_w, dt_proj_w, dt_proj_b, dt, Bm, Cm);
    // 6) chunked selective scan + gate -> y
    scan_phase1<<<(BSZ * DI * NCHUNK) / 8, 256>>>(dt, u, Bm, A_log, Hc, Dc);
    scan_phase2<<<(BSZ * DI) / 8, 256>>>(Hc, Dc, A_log, hs);
    scan_phase3<<<(BSZ * DI * NCHUNK) / 8, 256>>>(dt, u, Bm, Cm, A_log, Dp, xz, hs, y);
    // 7) out_proj -> t2
    gemm_nt<false, false><<<dim3(CDIM / 128, MROWS / 128), 256>>>(
        y, out_proj_w, nullptr, nullptr, t2, MROWS, CDIM, DI);
    // 8) cv2 + residual -> out (NCHW)
    gemm_nt<false, true><<<dim3(CDIM / 128, MROWS / 128), 256>>>(
        t2, cv2_w, cv2_b, x, out, MROWS, CDIM, CDIM);
}

// round 5
// speedup vs baseline: 4.2177x; 4.2177x over previous
#include <cuda_runtime.h>
#include <cuda_bf16.h>
#include <math.h>
#include <stdint.h>

// ---------------- problem constants ----------------
#define BSZ    2
#define CDIM   256
#define LIMG   4096
#define DI     512
#define DS     16
#define DR     16
#define NCHUNK 64
#define TCH    64
#define MROWS  8192

// ---------------- scratch ----------------
__device__ __nv_bfloat16 g_xT  [MROWS * CDIM];
__device__ __nv_bfloat16 g_wb1 [CDIM * CDIM];
__device__ __nv_bfloat16 g_wbin[2 * DI * CDIM];
__device__ __nv_bfloat16 g_wbo [CDIM * DI];
__device__ __nv_bfloat16 g_wb2 [CDIM * CDIM];
__device__ __nv_bfloat16 g_wxp [128 * DI];        // x_proj padded to 128 rows
__device__ __nv_bfloat16 g_wdt [DI * 32];         // dt_proj padded K 16->32
__device__ float         g_t0  [MROWS * CDIM];
__device__ __nv_bfloat16 g_t0b [MROWS * CDIM];
__device__ float         g_xz  [MROWS * 2 * DI];
__device__ float         g_u   [MROWS * DI];
__device__ __nv_bfloat16 g_ub  [MROWS * DI];
__device__ __nv_bfloat16 g_dtr [MROWS * 32];      // dt-rank (cols 16..31 zero)
__device__ float         g_dt  [MROWS * DI];
__device__ float         g_Bm  [MROWS * DS];
__device__ float         g_Cm  [MROWS * DS];
__device__ float         g_Hc  [BSZ * DI * NCHUNK * DS];
__device__ float         g_Dc  [BSZ * DI * NCHUNK];
__device__ float         g_hs  [BSZ * DI * NCHUNK * DS];
__device__ __nv_bfloat16 g_yb  [MROWS * DI];
__device__ __nv_bfloat16 g_t2b [MROWS * CDIM];

// ================= mma.sync bf16 NT GEMM =================
// C[m,n] = sum_k A[m,k]*W[n,k].  A:[M,K] bf16 rm, W:[N,K] bf16 rm. K % 32 == 0.
// OUTMODE 0: fp32 rm (+bias opt)   1: bf16 rm (+bias opt)
//         2: fp32 image (b*N+n)*LIMG+l, +bias +resid
//         3: fp32 rm, softplus(v + bias)
//         4: x_proj split: cols<16 -> dtr bf16[m][32] (16..31 zeroed),
//            16..31 -> Bm fp32[m][16], 32..47 -> Cm fp32[m][16]
#define SMEM_BYTES 33536

__device__ __forceinline__ uint32_t swz(int r, int c) {
    return (uint32_t)((r << 6) + ((c ^ ((r >> 1) & 3)) << 4));
}

#define LDSM4(R0,R1,R2,R3,ADDR) \
    asm volatile("ldmatrix.sync.aligned.m8n8.x4.shared.b16 {%0,%1,%2,%3},[%4];" \
                 : "=r"(R0),"=r"(R1),"=r"(R2),"=r"(R3) : "r"(ADDR))

#define MMA16816(D,A,B) \
    asm volatile("mma.sync.aligned.m16n8k16.row.col.f32.bf16.bf16.f32 " \
                 "{%0,%1,%2,%3},{%4,%5,%6,%7},{%8,%9},{%0,%1,%2,%3};" \
                 : "+f"((D)[0]),"+f"((D)[1]),"+f"((D)[2]),"+f"((D)[3]) \
                 : "r"((A)[0]),"r"((A)[1]),"r"((A)[2]),"r"((A)[3]), \
                   "r"((B)[0]),"r"((B)[1]))

template<int OUTMODE>
__global__ void __launch_bounds__(256, 2) gemm_mma(
    const __nv_bfloat16* __restrict__ A, const __nv_bfloat16* __restrict__ W,
    const float* __restrict__ bias, const float* __restrict__ resid,
    void* __restrict__ outp, float* __restrict__ out2, float* __restrict__ out3,
    int M, int N, int K)
{
    extern __shared__ char smem[];
    uint32_t sb = (uint32_t)__cvta_generic_to_shared(smem);
    int tid = threadIdx.x, wid = tid >> 5, lane = tid & 31;
    int wm = wid & 3, wn = wid >> 2;
    int m0 = blockIdx.y * 128, n0 = blockIdx.x * 128;

    float d[2][8][4];
#pragma unroll
    for (int i = 0; i < 2; i++)
#pragma unroll
        for (int j = 0; j < 8; j++)
#pragma unroll
            for (int q = 0; q < 4; q++) d[i][j][q] = 0.f;

    const int KIT = K >> 5;
    // loader lambda
    auto load_stage = [&](int kc, int s) {
        const __nv_bfloat16* Ap = A + (size_t)m0 * K + (kc << 5);
        const __nv_bfloat16* Wp = W + (size_t)n0 * K + (kc << 5);
        uint32_t sA = sb + s * 16384;
        uint32_t sW = sA + 8192;
#pragma unroll
        for (int i = 0; i < 2; i++) {
            int idx = tid + (i << 8);
            int r = idx >> 2, c = idx & 3;
            uint32_t so = swz(r, c);
            asm volatile("cp.async.cg.shared.global [%0],[%1],16;"
                         :: "r"(sA + so), "l"(Ap + (size_t)r * K + (c << 3)));
            asm volatile("cp.async.cg.shared.global [%0],[%1],16;"
                         :: "r"(sW + so), "l"(Wp + (size_t)r * K + (c << 3)));
        }
    };

    load_stage(0, 0);
    asm volatile("cp.async.commit_group;");

    int rowin = lane & 7, jm = lane >> 3;
    for (int kc = 0; kc < KIT; kc++) {
        if (kc + 1 < KIT) load_stage(kc + 1, (kc + 1) & 1);
        asm volatile("cp.async.commit_group;");
        asm volatile("cp.async.wait_group 1;");
        __syncthreads();

        uint32_t sA = sb + (kc & 1) * 16384;
        uint32_t sW = sA + 8192;
#pragma unroll
        for (int ks = 0; ks < 2; ks++) {
            uint32_t a[2][4];
            int chunk = (ks << 1) + (jm >> 1);
#pragma unroll
            for (int mt = 0; mt < 2; mt++) {
                int row = (wm << 5) + (mt << 4) + ((jm & 1) << 3) + rowin;
                LDSM4(a[mt][0], a[mt][1], a[mt][2], a[mt][3], sA + swz(row, chunk));
            }
            uint32_t bq[8][2];
#pragma unroll
            for (int p = 0; p < 4; p++) {
                int row = (wn << 6) + (p << 4) + ((jm & 1) << 3) + rowin;
                uint32_t q0, q1, q2, q3;
                LDSM4(q0, q1, q2, q3, sW + swz(row, chunk));
                bq[2 * p][0] = q0; bq[2 * p + 1][0] = q1;
                bq[2 * p][1] = q2; bq[2 * p + 1][1] = q3;
            }
#pragma unroll
            for (int mt = 0; mt < 2; mt++)
#pragma unroll
                for (int nt = 0; nt < 8; nt++)
                    MMA16816(d[mt][nt], a[mt], bq[nt]);
        }
        __syncthreads();
    }

    // epilogue: stage 128x64 halves via smem (stride 65 floats)
    float* stg = (float*)smem;
#pragma unroll
    for (int h = 0; h < 2; h++) {
        if (wn == h) {
#pragma unroll
            for (int mt = 0; mt < 2; mt++)
#pragma unroll
                for (int nt = 0; nt < 8; nt++)
#pragma unroll
                    for (int q = 0; q < 4; q++) {
                        int r  = (wm << 5) + (mt << 4) + (lane >> 2) + ((q >> 1) << 3);
                        int cc = (nt << 3) + ((lane & 3) << 1) + (q & 1);
                        stg[r * 65 + cc] = d[mt][nt][q];
                    }
        }
        __syncthreads();

        if (OUTMODE == 4) {
            if (h == 0) {
#pragma unroll
                for (int i = 0; i < 32; i++) {
                    int idx = (i << 8) + tid;
                    int cc = idx & 63, rw = idx >> 6;
                    float v = stg[rw * 65 + cc];
                    int row = m0 + rw;
                    __nv_bfloat16* dtr = (__nv_bfloat16*)outp;
                    if (cc < 16) dtr[(size_t)row * 32 + cc] = __float2bfloat16(v);
                    else if (cc < 32) { out2[(size_t)row * 16 + cc - 16] = v;
                                        dtr[(size_t)row * 32 + cc] = __float2bfloat16(0.f); }
                    else if (cc < 48) out3[(size_t)row * 16 + cc - 32] = v;
                }
            }
        } else if (OUTMODE == 2) {
            float* out = (float*)outp;
            int bI = m0 / LIMG, l0 = m0 % LIMG;
#pragma unroll
            for (int i = 0; i < 32; i++) {
                int idx = (i << 8) + tid;
                int rw = idx & 127, col = idx >> 7;
                float v = stg[rw * 65 + col] + bias[n0 + (h << 6) + col];
                size_t o = (size_t)(bI * N + n0 + (h << 6) + col) * LIMG + l0 + rw;
                out[o] = v + resid[o];
            }
        } else {
#pragma unroll
            for (int i = 0; i < 32; i++) {
                int idx = (i << 8) + tid;
                int cc = idx & 63, rw = idx >> 6;
                float v = stg[rw * 65 + cc];
                int col = n0 + (h << 6) + cc;
                if (OUTMODE == 3) {
                    float s = v + bias[col];
                    v = (s > 20.f) ? s : log1pf(expf(s));
                    ((float*)outp)[(size_t)(m0 + rw) * N + col] = v;
                } else {
                    if (bias) v += bias[col];
                    if (OUTMODE == 1)
                        ((__nv_bfloat16*)outp)[(size_t)(m0 + rw) * N + col] = __float2bfloat16(v);
                    else
                        ((float*)outp)[(size_t)(m0 + rw) * N + col] = v;
                }
            }
        }
        __syncthreads();
    }
}

// ================= converters / padders =================
__global__ void __launch_bounds__(256) f2bf(const float* __restrict__ in,
                                            __nv_bfloat16* __restrict__ out, int n)
{
    int i = blockIdx.x * 256 + threadIdx.x;
    if (i < n) out[i] = __float2bfloat16(in[i]);
}
__global__ void __launch_bounds__(256) pad_xp(const float* __restrict__ w,
                                              __nv_bfloat16* __restrict__ o)
{
    int i = blockIdx.x * 256 + threadIdx.x;   // 128*512
    int r = i >> 9, c = i & 511;
    o[i] = __float2bfloat16(r < 48 ? w[r * DI + c] : 0.f);
}
__global__ void __launch_bounds__(256) pad_dt(const float* __restrict__ w,
                                              __nv_bfloat16* __restrict__ o)
{
    int i = blockIdx.x * 256 + threadIdx.x;   // 512*32
    int r = i >> 5, c = i & 31;
    o[i] = __float2bfloat16(c < 16 ? w[r * DR + c] : 0.f);
}

// NCHW x -> row-major bf16 [b*L + l][c]
__global__ void __launch_bounds__(256) xpose(const float* __restrict__ x,
                                             __nv_bfloat16* __restrict__ xT)
{
    __shared__ float t[32][33];
    int l0 = blockIdx.x << 5, c0 = blockIdx.y << 5, b = blockIdx.z;
    int tx = threadIdx.x, ty = threadIdx.y;
#pragma unroll
    for (int j = 0; j < 32; j += 8)
        t[ty + j][tx] = x[((size_t)(b * CDIM + c0 + ty + j)) * LIMG + l0 + tx];
    __syncthreads();
#pragma unroll
    for (int j = 0; j < 32; j += 8)
        xT[((size_t)(b * LIMG + l0 + ty + j)) * CDIM + c0 + tx] = __float2bfloat16(t[tx][ty + j]);
}

// ================= LayerNorm (fp32 in -> bf16 out) =================
__global__ void __launch_bounds__(256) ln_kernel(
    const float* __restrict__ t0, __nv_bfloat16* __restrict__ t0b,
    const float* __restrict__ gam, const float* __restrict__ bet)
{
    int m = blockIdx.x;
    int c = threadIdx.x;
    float v = t0[(size_t)m * CDIM + c];
    float s1 = v, s2 = v * v;
#pragma unroll
    for (int off = 16; off; off >>= 1) {
        s1 += __shfl_xor_sync(0xffffffffu, s1, off);
        s2 += __shfl_xor_sync(0xffffffffu, s2, off);
    }
    __shared__ float a1[8], a2[8], mv[2];
    int wid = c >> 5, lane = c & 31;
    if (lane == 0) { a1[wid] = s1; a2[wid] = s2; }
    __syncthreads();
    if (c == 0) {
        float x1 = 0.f, x2 = 0.f;
        for (int i = 0; i < 8; i++) { x1 += a1[i]; x2 += a2[i]; }
        float mu = x1 * (1.f / CDIM);
        mv[0] = mu;
        mv[1] = rsqrtf(x2 * (1.f / CDIM) - mu * mu + 1e-5f);
    }
    __syncthreads();
    t0b[(size_t)m * CDIM + c] = __float2bfloat16((v - mv[0]) * mv[1] * gam[c] + bet[c]);
}

// ================= sliding-window depthwise conv + SiLU =================
#define CLSEG 64
__global__ void __launch_bounds__(512) conv_silu_kernel(
    const float* __restrict__ xz, const float* __restrict__ cw,
    const float* __restrict__ cb, float* __restrict__ u, __nv_bfloat16* __restrict__ ub)
{
    int b = blockIdx.y, d = threadIdx.x;
    int l0 = blockIdx.x * CLSEG;
    float w0 = cw[d * 4 + 0], w1 = cw[d * 4 + 1], w2 = cw[d * 4 + 2], w3 = cw[d * 4 + 3];
    float bia = cb[d];
    size_t rb = (size_t)(b * LIMG) * (2 * DI) + d;
    float x0 = (l0 >= 3) ? xz[rb + (size_t)(l0 - 3) * (2 * DI)] : 0.f;
    float x1 = (l0 >= 2) ? xz[rb + (size_t)(l0 - 2) * (2 * DI)] : 0.f;
    float x2 = (l0 >= 1) ? xz[rb + (size_t)(l0 - 1) * (2 * DI)] : 0.f;
    for (int i = 0; i < CLSEG; i++) {
        float x3 = xz[rb + (size_t)(l0 + i) * (2 * DI)];
        float s = bia + w0 * x0 + w1 * x1 + w2 * x2 + w3 * x3;
        float sig = 1.f / (1.f + __expf(-s));
        float uv = s * sig;
        size_t o = (size_t)(b * LIMG + l0 + i) * DI + d;
        u[o]  = uv;
        ub[o] = __float2bfloat16(uv);
        x0 = x1; x1 = x2; x2 = x3;
    }
}

// ================= chunked selective scan =================
__global__ void __launch_bounds__(512) scan_phase1(
    const float* __restrict__ dt, const float* __restrict__ u,
    const float* __restrict__ Bm, const float* __restrict__ A_log,
    float* __restrict__ Hc, float* __restrict__ Dc)
{
    __shared__ float Bs[TCH][DS];
    int c = blockIdx.x, b = blockIdx.y, d = threadIdx.x;
    for (int idx = d; idx < TCH * DS; idx += 512)
        Bs[idx >> 4][idx & 15] = Bm[(size_t)(b * LIMG + c * TCH) * DS + idx];
    __syncthreads();

    float A[DS], h[DS];
    bool fast = true;
#pragma unroll
    for (int n = 0; n < DS; n++) {
        A[n] = -expf(A_log[d * DS + n]);
        h[n] = 0.f;
        fast = fast && (fabsf(A[n] + (float)(n + 1)) < 1e-3f * (n + 1));
    }
    float S = 0.f;
    size_t base = (size_t)(b * LIMG + c * TCH) * DI + d;
    if (fast) {
        for (int i = 0; i < TCH; i++) {
            float dtv = dt[base + (size_t)i * DI];
            float uv  = u [base + (size_t)i * DI];
            float du  = dtv * uv;
            S += dtv;
            float w = __expf(-dtv), e = 1.f;
#pragma unroll
            for (int n = 0; n < DS; n++) {
                e *= w;
                h[n] = e * h[n] + du * Bs[i][n];
            }
        }
    } else {
        for (int i = 0; i < TCH; i++) {
            float dtv = dt[base + (size_t)i * DI];
            float uv  = u [base + (size_t)i * DI];
            float du  = dtv * uv;
            S += dtv;
#pragma unroll
            for (int n = 0; n < DS; n++)
                h[n] = __expf(dtv * A[n]) * h[n] + du * Bs[i][n];
        }
    }
    size_t o = ((size_t)(b * DI + d) * NCHUNK + c) * DS;
#pragma unroll
    for (int n = 0; n < DS; n++) Hc[o + n] = h[n];
    Dc[(b * DI + d) * NCHUNK + c] = S;
}

__global__ void __launch_bounds__(256) scan_phase2(
    const float* __restrict__ Hc, const float* __restrict__ Dc,
    const float* __restrict__ A_log, float* __restrict__ hstart)
{
    int gw   = (blockIdx.x * 256 + threadIdx.x) >> 5;
    int lane = threadIdx.x & 31;
    int n    = lane & 15;
    int d    = gw & (DI - 1);
    float An = -expf(A_log[d * DS + n]);
    float hs = 0.f;
    size_t bb = (size_t)gw * NCHUNK;
    for (int c = 0; c < NCHUNK; c++) {
        if (lane < 16) hstart[(bb + c) * DS + n] = hs;
        float Hv = Hc[(bb + c) * DS + n];
        float Dv = Dc[bb + c];
        hs = __expf(An * Dv) * hs + Hv;
    }
}

__global__ void __launch_bounds__(512) scan_phase3(
    const float* __restrict__ dt, const float* __restrict__ u,
    const float* __restrict__ Bm, const float* __restrict__ Cm,
    const float* __restrict__ A_log, const float* __restrict__ Dpar,
    const float* __restrict__ xz, const float* __restrict__ hstart,
    __nv_bfloat16* __restrict__ yb)
{
    __shared__ float Bs[TCH][DS], Cs[TCH][DS];
    int c = blockIdx.x, b = blockIdx.y, d = threadIdx.x;
    for (int idx = d; idx < TCH * DS; idx += 512) {
        size_t g = (size_t)(b * LIMG + c * TCH) * DS + idx;
        Bs[idx >> 4][idx & 15] = Bm[g];
        Cs[idx >> 4][idx & 15] = Cm[g];
    }
    __syncthreads();

    float A[DS], h[DS];
    bool fast = true;
    size_t ho = ((size_t)(b * DI + d) * NCHUNK + c) * DS;
#pragma unroll
    for (int n = 0; n < DS; n++) {
        A[n] = -expf(A_log[d * DS + n]);
        h[n] = hstart[ho + n];
        fast = fast && (fabsf(A[n] + (float)(n + 1)) < 1e-3f * (n + 1));
    }
    float Dd = Dpar[d];
    size_t base  = (size_t)(b * LIMG + c * TCH) * DI + d;
    size_t basez = (size_t)(b * LIMG + c * TCH) * (2 * DI) + DI + d;
    for (int i = 0; i < TCH; i++) {
        float dtv = dt[base + (size_t)i * DI];
        float uv  = u [base + (size_t)i * DI];
        float du  = dtv * uv;
        float acc = 0.f;
        if (fast) {
            float w = __expf(-dtv), e = 1.f;
#pragma unroll
            for (int n = 0; n < DS; n++) {
                e *= w;
                h[n] = e * h[n] + du * Bs[i][n];
                acc += h[n] * Cs[i][n];
            }
        } else {
#pragma unroll
            for (int n = 0; n < DS; n++) {
                h[n] = __expf(dtv * A[n]) * h[n] + du * Bs[i][n];
                acc += h[n] * Cs[i][n];
            }
        }
        float zv  = xz[basez + (size_t)i * (2 * DI)];
        float sig = 1.f / (1.f + __expf(-zv));
        float yy  = (acc + uv * Dd) * (zv * sig);
        yb[base + (size_t)i * DI] = __float2bfloat16(yy);
    }
}

// ================= launch =================
extern "C" void kernel_launch(void* const* d_in, const int* in_sizes, int n_in,
                              void* d_out, int out_size)
{
    (void)in_sizes; (void)n_in; (void)out_size;
    const float* x         = (const float*)d_in[0];
    const float* cv1_w     = (const float*)d_in[1];
    const float* cv1_b     = (const float*)d_in[2];
    const float* ln_g      = (const float*)d_in[3];
    const float* ln_b      = (const float*)d_in[4];
    const float* in_proj_w = (const float*)d_in[5];
    const float* conv_w    = (const float*)d_in[6];
    const float* conv_b    = (const float*)d_in[7];
    const float* x_proj_w  = (const float*)d_in[8];
    const float* dt_proj_w = (const float*)d_in[9];
    const float* dt_proj_b = (const float*)d_in[10];
    const float* A_log     = (const float*)d_in[11];
    const float* Dp        = (const float*)d_in[12];
    const float* out_proj_w= (const float*)d_in[13];
    const float* cv2_w     = (const float*)d_in[14];
    const float* cv2_b     = (const float*)d_in[15];
    float* out = (float*)d_out;

    __nv_bfloat16 *xT, *wb1, *wbin, *wbo, *wb2, *wxp, *wdt, *t0b, *ub, *dtr, *yb, *t2b;
    float *t0, *xz, *u, *dt, *Bm, *Cm, *Hc, *Dc, *hs;
    cudaGetSymbolAddress((void**)&xT,  g_xT);
    cudaGetSymbolAddress((void**)&wb1, g_wb1);
    cudaGetSymbolAddress((void**)&wbin,g_wbin);
    cudaGetSymbolAddress((void**)&wbo, g_wbo);
    cudaGetSymbolAddress((void**)&wb2, g_wb2);
    cudaGetSymbolAddress((void**)&wxp, g_wxp);
    cudaGetSymbolAddress((void**)&wdt, g_wdt);
    cudaGetSymbolAddress((void**)&t0,  g_t0);
    cudaGetSymbolAddress((void**)&t0b, g_t0b);
    cudaGetSymbolAddress((void**)&xz,  g_xz);
    cudaGetSymbolAddress((void**)&u,   g_u);
    cudaGetSymbolAddress((void**)&ub,  g_ub);
    cudaGetSymbolAddress((void**)&dtr, g_dtr);
    cudaGetSymbolAddress((void**)&dt,  g_dt);
    cudaGetSymbolAddress((void**)&Bm,  g_Bm);
    cudaGetSymbolAddress((void**)&Cm,  g_Cm);
    cudaGetSymbolAddress((void**)&Hc,  g_Hc);
    cudaGetSymbolAddress((void**)&Dc,  g_Dc);
    cudaGetSymbolAddress((void**)&hs,  g_hs);
    cudaGetSymbolAddress((void**)&yb,  g_yb);
    cudaGetSymbolAddress((void**)&t2b, g_t2b);

    // weight conversions / padding
    f2bf<<<(CDIM*CDIM + 255)/256, 256>>>(cv1_w, wb1, CDIM*CDIM);
    f2bf<<<(2*DI*CDIM + 255)/256, 256>>>(in_proj_w, wbin, 2*DI*CDIM);
    f2bf<<<(CDIM*DI + 255)/256, 256>>>(out_proj_w, wbo, CDIM*DI);
    f2bf<<<(CDIM*CDIM + 255)/256, 256>>>(cv2_w, wb2, CDIM*CDIM);
    pad_xp<<<(128*DI)/256, 256>>>(x_proj_w, wxp);
    pad_dt<<<(DI*32)/256, 256>>>(dt_proj_w, wdt);
    xpose<<<dim3(LIMG/32, CDIM/32, BSZ), dim3(32, 8)>>>(x, xT);

    // cv1 -> t0 fp32
    gemm_mma<0><<<dim3(CDIM/128, MROWS/128), 256, SMEM_BYTES>>>(
        xT, wb1, cv1_b, nullptr, t0, nullptr, nullptr, MROWS, CDIM, CDIM);
    // LN -> bf16
    ln_kernel<<<MROWS, 256>>>(t0, t0b, ln_g, ln_b);
    // in_proj -> xz fp32
    gemm_mma<0><<<dim3(2*DI/128, MROWS/128), 256, SMEM_BYTES>>>(
        t0b, wbin, nullptr, nullptr, xz, nullptr, nullptr, MROWS, 2*DI, CDIM);
    // conv + silu -> u fp32 / ub bf16
    conv_silu_kernel<<<dim3(LIMG/CLSEG, BSZ), 512>>>(xz, conv_w, conv_b, u, ub);
    // x_proj GEMM -> dtr(bf16) / Bm / Cm
    gemm_mma<4><<<dim3(1, MROWS/128), 256, SMEM_BYTES>>>(
        ub, wxp, nullptr, nullptr, dtr, Bm, Cm, MROWS, 128, DI);
    // dt_proj GEMM + bias + softplus -> dt fp32
    gemm_mma<3><<<dim3(DI/128, MROWS/128), 256, SMEM_BYTES>>>(
        dtr, wdt, dt_proj_b, nullptr, dt, nullptr, nullptr, MROWS, DI, 32);
    // chunked scan
    scan_phase1<<<dim3(NCHUNK, BSZ), 512>>>(dt, u, Bm, A_log, Hc, Dc);
    scan_phase2<<<(BSZ*DI)/8, 256>>>(Hc, Dc, A_log, hs);
    scan_phase3<<<dim3(NCHUNK, BSZ), 512>>>(dt, u, Bm, Cm, A_log, Dp, xz, hs, yb);
    // out_proj -> t2b bf16
    gemm_mma<1><<<dim3(CDIM/128, MROWS/128), 256, SMEM_BYTES>>>(
        yb, wbo, nullptr, nullptr, t2b, nullptr, nullptr, MROWS, CDIM, DI);
    // cv2 + bias + residual -> out image
    gemm_mma<2><<<dim3(CDIM/128, MROWS/128), 256, SMEM_BYTES>>>(
        t2b, wb2, cv2_b, x, out, nullptr, nullptr, MROWS, CDIM, CDIM);
}

// round 6
// speedup vs baseline: 4.7904x; 1.1358x over previous
#include <cuda_runtime.h>
#include <cuda_bf16.h>
#include <math.h>
#include <stdint.h>

// ---------------- problem constants ----------------
#define BSZ    2
#define CDIM   256
#define LIMG   4096
#define DI     512
#define DS     16
#define DR     16
#define NCHUNK 64
#define TCH    64
#define MROWS  8192

// ---------------- scratch ----------------
__device__ __nv_bfloat16 g_xT  [MROWS * CDIM];
__device__ __nv_bfloat16 g_wb1 [CDIM * CDIM];
__device__ __nv_bfloat16 g_wbin[2 * DI * CDIM];
__device__ __nv_bfloat16 g_wbo [CDIM * DI];
__device__ __nv_bfloat16 g_wb2 [CDIM * CDIM];
__device__ __nv_bfloat16 g_wxp [128 * DI];
__device__ __nv_bfloat16 g_wdt [DI * 32];
__device__ __nv_bfloat16 g_t0a [MROWS * CDIM];     // cv1 out (pre-LN)
__device__ __nv_bfloat16 g_t0b [MROWS * CDIM];     // LN out
__device__ __nv_bfloat16 g_xz  [MROWS * 2 * DI];   // in_proj out (bf16 now)
__device__ __nv_bfloat16 g_ub  [MROWS * DI];       // silu(conv)
__device__ __nv_bfloat16 g_dtr [MROWS * 32];       // dt-rank (cols 16..31 zero)
__device__ __nv_bfloat16 g_dtb [MROWS * DI];       // softplus dt (bf16 now)
__device__ float         g_Bm  [MROWS * DS];
__device__ float         g_Cm  [MROWS * DS];
__device__ float         g_Hc  [BSZ * DI * NCHUNK * DS];
__device__ float         g_Dc  [BSZ * DI * NCHUNK];
__device__ float         g_hs  [BSZ * DI * NCHUNK * DS];
__device__ __nv_bfloat16 g_yb  [MROWS * DI];
__device__ __nv_bfloat16 g_t2b [MROWS * CDIM];

// ================= mma.sync bf16 NT GEMM =================
// C[m,n] = sum_k A[m,k]*W[n,k].  A:[M,K] bf16 rm, W:[N,K] bf16 rm. K % 32 == 0.
// OUTMODE 0: fp32 rm (+bias opt)   1: bf16 rm (+bias opt)
//         2: fp32 image (b*N+n)*LIMG+l, +bias +resid
//         3: bf16 rm, softplus(v + bias)
//         4: x_proj split: cols<16 -> dtr bf16[m][32] (16..31 zeroed),
//            16..31 -> Bm fp32[m][16], 32..47 -> Cm fp32[m][16]
#define SMEM_BYTES 33536

__device__ __forceinline__ uint32_t swz(int r, int c) {
    return (uint32_t)((r << 6) + ((c ^ ((r >> 1) & 3)) << 4));
}

#define LDSM4(R0,R1,R2,R3,ADDR) \
    asm volatile("ldmatrix.sync.aligned.m8n8.x4.shared.b16 {%0,%1,%2,%3},[%4];" \
                 : "=r"(R0),"=r"(R1),"=r"(R2),"=r"(R3) : "r"(ADDR))

#define MMA16816(D,A,B) \
    asm volatile("mma.sync.aligned.m16n8k16.row.col.f32.bf16.bf16.f32 " \
                 "{%0,%1,%2,%3},{%4,%5,%6,%7},{%8,%9},{%0,%1,%2,%3};" \
                 : "+f"((D)[0]),"+f"((D)[1]),"+f"((D)[2]),"+f"((D)[3]) \
                 : "r"((A)[0]),"r"((A)[1]),"r"((A)[2]),"r"((A)[3]), \
                   "r"((B)[0]),"r"((B)[1]))

template<int OUTMODE>
__global__ void __launch_bounds__(256, 2) gemm_mma(
    const __nv_bfloat16* __restrict__ A, const __nv_bfloat16* __restrict__ W,
    const float* __restrict__ bias, const float* __restrict__ resid,
    void* __restrict__ outp, float* __restrict__ out2, float* __restrict__ out3,
    int M, int N, int K)
{
    extern __shared__ char smem[];
    uint32_t sb = (uint32_t)__cvta_generic_to_shared(smem);
    int tid = threadIdx.x, wid = tid >> 5, lane = tid & 31;
    int wm = wid & 3, wn = wid >> 2;
    int m0 = blockIdx.y * 128, n0 = blockIdx.x * 128;

    float d[2][8][4];
#pragma unroll
    for (int i = 0; i < 2; i++)
#pragma unroll
        for (int j = 0; j < 8; j++)
#pragma unroll
            for (int q = 0; q < 4; q++) d[i][j][q] = 0.f;

    const int KIT = K >> 5;
    auto load_stage = [&](int kc, int s) {
        const __nv_bfloat16* Ap = A + (size_t)m0 * K + (kc << 5);
        const __nv_bfloat16* Wp = W + (size_t)n0 * K + (kc << 5);
        uint32_t sA = sb + s * 16384;
        uint32_t sW = sA + 8192;
#pragma unroll
        for (int i = 0; i < 2; i++) {
            int idx = tid + (i << 8);
            int r = idx >> 2, c = idx & 3;
            uint32_t so = swz(r, c);
            asm volatile("cp.async.cg.shared.global [%0],[%1],16;"
                         :: "r"(sA + so), "l"(Ap + (size_t)r * K + (c << 3)));
            asm volatile("cp.async.cg.shared.global [%0],[%1],16;"
                         :: "r"(sW + so), "l"(Wp + (size_t)r * K + (c << 3)));
        }
    };

    load_stage(0, 0);
    asm volatile("cp.async.commit_group;");

    int rowin = lane & 7, jm = lane >> 3;
    for (int kc = 0; kc < KIT; kc++) {
        if (kc + 1 < KIT) load_stage(kc + 1, (kc + 1) & 1);
        asm volatile("cp.async.commit_group;");
        asm volatile("cp.async.wait_group 1;");
        __syncthreads();

        uint32_t sA = sb + (kc & 1) * 16384;
        uint32_t sW = sA + 8192;
#pragma unroll
        for (int ks = 0; ks < 2; ks++) {
            uint32_t a[2][4];
            int chunk = (ks << 1) + (jm >> 1);
#pragma unroll
            for (int mt = 0; mt < 2; mt++) {
                int row = (wm << 5) + (mt << 4) + ((jm & 1) << 3) + rowin;
                LDSM4(a[mt][0], a[mt][1], a[mt][2], a[mt][3], sA + swz(row, chunk));
            }
            uint32_t bq[8][2];
#pragma unroll
            for (int p = 0; p < 4; p++) {
                int row = (wn << 6) + (p << 4) + ((jm & 1) << 3) + rowin;
                uint32_t q0, q1, q2, q3;
                LDSM4(q0, q1, q2, q3, sW + swz(row, chunk));
                bq[2 * p][0] = q0; bq[2 * p + 1][0] = q1;
                bq[2 * p][1] = q2; bq[2 * p + 1][1] = q3;
            }
#pragma unroll
            for (int mt = 0; mt < 2; mt++)
#pragma unroll
                for (int nt = 0; nt < 8; nt++)
                    MMA16816(d[mt][nt], a[mt], bq[nt]);
        }
        __syncthreads();
    }

    // epilogue: stage 128x64 halves via smem (stride 65 floats)
    float* stg = (float*)smem;
#pragma unroll
    for (int h = 0; h < 2; h++) {
        if (wn == h) {
#pragma unroll
            for (int mt = 0; mt < 2; mt++)
#pragma unroll
                for (int nt = 0; nt < 8; nt++)
#pragma unroll
                    for (int q = 0; q < 4; q++) {
                        int r  = (wm << 5) + (mt << 4) + (lane >> 2) + ((q >> 1) << 3);
                        int cc = (nt << 3) + ((lane & 3) << 1) + (q & 1);
                        stg[r * 65 + cc] = d[mt][nt][q];
                    }
        }
        __syncthreads();

        if (OUTMODE == 4) {
            if (h == 0) {
#pragma unroll
                for (int i = 0; i < 32; i++) {
                    int idx = (i << 8) + tid;
                    int cc = idx & 63, rw = idx >> 6;
                    float v = stg[rw * 65 + cc];
                    int row = m0 + rw;
                    __nv_bfloat16* dtr = (__nv_bfloat16*)outp;
                    if (cc < 16) dtr[(size_t)row * 32 + cc] = __float2bfloat16(v);
                    else if (cc < 32) { out2[(size_t)row * 16 + cc - 16] = v;
                                        dtr[(size_t)row * 32 + cc] = __float2bfloat16(0.f); }
                    else if (cc < 48) out3[(size_t)row * 16 + cc - 32] = v;
                }
            }
        } else if (OUTMODE == 2) {
            float* out = (float*)outp;
            int bI = m0 / LIMG, l0 = m0 % LIMG;
#pragma unroll
            for (int i = 0; i < 32; i++) {
                int idx = (i << 8) + tid;
                int rw = idx & 127, col = idx >> 7;
                float v = stg[rw * 65 + col] + bias[n0 + (h << 6) + col];
                size_t o = (size_t)(bI * N + n0 + (h << 6) + col) * LIMG + l0 + rw;
                out[o] = v + resid[o];
            }
        } else {
#pragma unroll
            for (int i = 0; i < 32; i++) {
                int idx = (i << 8) + tid;
                int cc = idx & 63, rw = idx >> 6;
                float v = stg[rw * 65 + cc];
                int col = n0 + (h << 6) + cc;
                if (OUTMODE == 3) {
                    float s = v + bias[col];
                    v = (s > 20.f) ? s : log1pf(expf(s));
                    ((__nv_bfloat16*)outp)[(size_t)(m0 + rw) * N + col] = __float2bfloat16(v);
                } else {
                    if (bias) v += bias[col];
                    if (OUTMODE == 1)
                        ((__nv_bfloat16*)outp)[(size_t)(m0 + rw) * N + col] = __float2bfloat16(v);
                    else
                        ((float*)outp)[(size_t)(m0 + rw) * N + col] = v;
                }
            }
        }
        __syncthreads();
    }
}

// ================= single fused weight-prep kernel =================
#define S_WB1  (CDIM*CDIM)
#define S_WBIN (2*DI*CDIM)
#define S_WBO  (CDIM*DI)
#define S_WB2  (CDIM*CDIM)
#define S_WXP  (128*DI)
#define S_WDT  (DI*32)
#define PREP_TOTAL (S_WB1+S_WBIN+S_WBO+S_WB2+S_WXP+S_WDT)
__global__ void __launch_bounds__(256) prep_weights(
    const float* __restrict__ cv1_w, const float* __restrict__ in_proj_w,
    const float* __restrict__ out_proj_w, const float* __restrict__ cv2_w,
    const float* __restrict__ x_proj_w, const float* __restrict__ dt_proj_w,
    __nv_bfloat16* __restrict__ wb1, __nv_bfloat16* __restrict__ wbin,
    __nv_bfloat16* __restrict__ wbo, __nv_bfloat16* __restrict__ wb2,
    __nv_bfloat16* __restrict__ wxp, __nv_bfloat16* __restrict__ wdt)
{
    int i = blockIdx.x * 256 + threadIdx.x;
    if (i < S_WB1) { wb1[i] = __float2bfloat16(cv1_w[i]); return; }
    i -= S_WB1;
    if (i < S_WBIN) { wbin[i] = __float2bfloat16(in_proj_w[i]); return; }
    i -= S_WBIN;
    if (i < S_WBO) { wbo[i] = __float2bfloat16(out_proj_w[i]); return; }
    i -= S_WBO;
    if (i < S_WB2) { wb2[i] = __float2bfloat16(cv2_w[i]); return; }
    i -= S_WB2;
    if (i < S_WXP) {
        int r = i >> 9, c = i & 511;
        wxp[i] = __float2bfloat16(r < 48 ? x_proj_w[r * DI + c] : 0.f);
        return;
    }
    i -= S_WXP;
    if (i < S_WDT) {
        int r = i >> 5, c = i & 31;
        wdt[i] = __float2bfloat16(c < 16 ? dt_proj_w[r * DR + c] : 0.f);
    }
}

// NCHW x -> row-major bf16 [b*L + l][c]
__global__ void __launch_bounds__(256) xpose(const float* __restrict__ x,
                                             __nv_bfloat16* __restrict__ xT)
{
    __shared__ float t[32][33];
    int l0 = blockIdx.x << 5, c0 = blockIdx.y << 5, b = blockIdx.z;
    int tx = threadIdx.x, ty = threadIdx.y;
#pragma unroll
    for (int j = 0; j < 32; j += 8)
        t[ty + j][tx] = x[((size_t)(b * CDIM + c0 + ty + j)) * LIMG + l0 + tx];
    __syncthreads();
#pragma unroll
    for (int j = 0; j < 32; j += 8)
        xT[((size_t)(b * LIMG + l0 + ty + j)) * CDIM + c0 + tx] = __float2bfloat16(t[tx][ty + j]);
}

// ================= LayerNorm (bf16 in -> bf16 out, fp32 stats) =================
__global__ void __launch_bounds__(256) ln_kernel(
    const __nv_bfloat16* __restrict__ t0, __nv_bfloat16* __restrict__ t0b,
    const float* __restrict__ gam, const float* __restrict__ bet)
{
    int m = blockIdx.x;
    int c = threadIdx.x;
    float v = __bfloat162float(t0[(size_t)m * CDIM + c]);
    float s1 = v, s2 = v * v;
#pragma unroll
    for (int off = 16; off; off >>= 1) {
        s1 += __shfl_xor_sync(0xffffffffu, s1, off);
        s2 += __shfl_xor_sync(0xffffffffu, s2, off);
    }
    __shared__ float a1[8], a2[8], mv[2];
    int wid = c >> 5, lane = c & 31;
    if (lane == 0) { a1[wid] = s1; a2[wid] = s2; }
    __syncthreads();
    if (c == 0) {
        float x1 = 0.f, x2 = 0.f;
        for (int i = 0; i < 8; i++) { x1 += a1[i]; x2 += a2[i]; }
        float mu = x1 * (1.f / CDIM);
        mv[0] = mu;
        mv[1] = rsqrtf(x2 * (1.f / CDIM) - mu * mu + 1e-5f);
    }
    __syncthreads();
    t0b[(size_t)m * CDIM + c] = __float2bfloat16((v - mv[0]) * mv[1] * gam[c] + bet[c]);
}

// ================= sliding-window depthwise conv + SiLU (bf16 in/out) =================
#define CLSEG 64
__global__ void __launch_bounds__(512) conv_silu_kernel(
    const __nv_bfloat16* __restrict__ xz, const float* __restrict__ cw,
    const float* __restrict__ cb, __nv_bfloat16* __restrict__ ub)
{
    int b = blockIdx.y, d = threadIdx.x;
    int l0 = blockIdx.x * CLSEG;
    float w0 = cw[d * 4 + 0], w1 = cw[d * 4 + 1], w2 = cw[d * 4 + 2], w3 = cw[d * 4 + 3];
    float bia = cb[d];
    size_t rb = (size_t)(b * LIMG) * (2 * DI) + d;
    float x0 = (l0 >= 3) ? __bfloat162float(xz[rb + (size_t)(l0 - 3) * (2 * DI)]) : 0.f;
    float x1 = (l0 >= 2) ? __bfloat162float(xz[rb + (size_t)(l0 - 2) * (2 * DI)]) : 0.f;
    float x2 = (l0 >= 1) ? __bfloat162float(xz[rb + (size_t)(l0 - 1) * (2 * DI)]) : 0.f;
    for (int i = 0; i < CLSEG; i++) {
        float x3 = __bfloat162float(xz[rb + (size_t)(l0 + i) * (2 * DI)]);
        float s = bia + w0 * x0 + w1 * x1 + w2 * x2 + w3 * x3;
        float sig = 1.f / (1.f + __expf(-s));
        ub[(size_t)(b * LIMG + l0 + i) * DI + d] = __float2bfloat16(s * sig);
        x0 = x1; x1 = x2; x2 = x3;
    }
}

// ================= chunked selective scan (bf16 dt/u/z) =================
__global__ void __launch_bounds__(512) scan_phase1(
    const __nv_bfloat16* __restrict__ dt, const __nv_bfloat16* __restrict__ u,
    const float* __restrict__ Bm, const float* __restrict__ A_log,
    float* __restrict__ Hc, float* __restrict__ Dc)
{
    __shared__ float Bs[TCH][DS];
    int c = blockIdx.x, b = blockIdx.y, d = threadIdx.x;
    for (int idx = d; idx < TCH * DS; idx += 512)
        Bs[idx >> 4][idx & 15] = Bm[(size_t)(b * LIMG + c * TCH) * DS + idx];
    __syncthreads();

    float A[DS], h[DS];
    bool fast = true;
#pragma unroll
    for (int n = 0; n < DS; n++) {
        A[n] = -expf(A_log[d * DS + n]);
        h[n] = 0.f;
        fast = fast && (fabsf(A[n] + (float)(n + 1)) < 1e-3f * (n + 1));
    }
    float S = 0.f;
    size_t base = (size_t)(b * LIMG + c * TCH) * DI + d;
    if (fast) {
        for (int i = 0; i < TCH; i++) {
            float dtv = __bfloat162float(dt[base + (size_t)i * DI]);
            float uv  = __bfloat162float(u [base + (size_t)i * DI]);
            float du  = dtv * uv;
            S += dtv;
            float w = __expf(-dtv), e = 1.f;
#pragma unroll
            for (int n = 0; n < DS; n++) {
                e *= w;
                h[n] = e * h[n] + du * Bs[i][n];
            }
        }
    } else {
        for (int i = 0; i < TCH; i++) {
            float dtv = __bfloat162float(dt[base + (size_t)i * DI]);
            float uv  = __bfloat162float(u [base + (size_t)i * DI]);
            float du  = dtv * uv;
            S += dtv;
#pragma unroll
            for (int n = 0; n < DS; n++)
                h[n] = __expf(dtv * A[n]) * h[n] + du * Bs[i][n];
        }
    }
    size_t o = ((size_t)(b * DI + d) * NCHUNK + c) * DS;
#pragma unroll
    for (int n = 0; n < DS; n++) Hc[o + n] = h[n];
    Dc[(b * DI + d) * NCHUNK + c] = S;
}

__global__ void __launch_bounds__(256) scan_phase2(
    const float* __restrict__ Hc, const float* __restrict__ Dc,
    const float* __restrict__ A_log, float* __restrict__ hstart)
{
    int gw   = (blockIdx.x * 256 + threadIdx.x) >> 5;
    int lane = threadIdx.x & 31;
    int n    = lane & 15;
    int d    = gw & (DI - 1);
    float An = -expf(A_log[d * DS + n]);
    float hs = 0.f;
    size_t bb = (size_t)gw * NCHUNK;
    for (int c = 0; c < NCHUNK; c++) {
        if (lane < 16) hstart[(bb + c) * DS + n] = hs;
        float Hv = Hc[(bb + c) * DS + n];
        float Dv = Dc[bb + c];
        hs = __expf(An * Dv) * hs + Hv;
    }
}

__global__ void __launch_bounds__(512) scan_phase3(
    const __nv_bfloat16* __restrict__ dt, const __nv_bfloat16* __restrict__ u,
    const float* __restrict__ Bm, const float* __restrict__ Cm,
    const float* __restrict__ A_log, const float* __restrict__ Dpar,
    const __nv_bfloat16* __restrict__ xz, const float* __restrict__ hstart,
    __nv_bfloat16* __restrict__ yb)
{
    __shared__ float Bs[TCH][DS], Cs[TCH][DS];
    int c = blockIdx.x, b = blockIdx.y, d = threadIdx.x;
    for (int idx = d; idx < TCH * DS; idx += 512) {
        size_t g = (size_t)(b * LIMG + c * TCH) * DS + idx;
        Bs[idx >> 4][idx & 15] = Bm[g];
        Cs[idx >> 4][idx & 15] = Cm[g];
    }
    __syncthreads();

    float A[DS], h[DS];
    bool fast = true;
    size_t ho = ((size_t)(b * DI + d) * NCHUNK + c) * DS;
#pragma unroll
    for (int n = 0; n < DS; n++) {
        A[n] = -expf(A_log[d * DS + n]);
        h[n] = hstart[ho + n];
        fast = fast && (fabsf(A[n] + (float)(n + 1)) < 1e-3f * (n + 1));
    }
    float Dd = Dpar[d];
    size_t base  = (size_t)(b * LIMG + c * TCH) * DI + d;
    size_t basez = (size_t)(b * LIMG + c * TCH) * (2 * DI) + DI + d;
    for (int i = 0; i < TCH; i++) {
        float dtv = __bfloat162float(dt[base + (size_t)i * DI]);
        float uv  = __bfloat162float(u [base + (size_t)i * DI]);
        float du  = dtv * uv;
        float acc = 0.f;
        if (fast) {
            float w = __expf(-dtv), e = 1.f;
#pragma unroll
            for (int n = 0; n < DS; n++) {
                e *= w;
                h[n] = e * h[n] + du * Bs[i][n];
                acc += h[n] * Cs[i][n];
            }
        } else {
#pragma unroll
            for (int n = 0; n < DS; n++) {
                h[n] = __expf(dtv * A[n]) * h[n] + du * Bs[i][n];
                acc += h[n] * Cs[i][n];
            }
        }
        float zv  = __bfloat162float(xz[basez + (size_t)i * (2 * DI)]);
        float sig = 1.f / (1.f + __expf(-zv));
        float yy  = (acc + uv * Dd) * (zv * sig);
        yb[base + (size_t)i * DI] = __float2bfloat16(yy);
    }
}

// ================= launch =================
extern "C" void kernel_launch(void* const* d_in, const int* in_sizes, int n_in,
                              void* d_out, int out_size)
{
    (void)in_sizes; (void)n_in; (void)out_size;
    const float* x         = (const float*)d_in[0];
    const float* cv1_w     = (const float*)d_in[1];
    const float* cv1_b     = (const float*)d_in[2];
    const float* ln_g      = (const float*)d_in[3];
    const float* ln_b      = (const float*)d_in[4];
    const float* in_proj_w = (const float*)d_in[5];
    const float* conv_w    = (const float*)d_in[6];
    const float* conv_b    = (const float*)d_in[7];
    const float* x_proj_w  = (const float*)d_in[8];
    const float* dt_proj_w = (const float*)d_in[9];
    const float* dt_proj_b = (const float*)d_in[10];
    const float* A_log     = (const float*)d_in[11];
    const float* Dp        = (const float*)d_in[12];
    const float* out_proj_w= (const float*)d_in[13];
    const float* cv2_w     = (const float*)d_in[14];
    const float* cv2_b     = (const float*)d_in[15];
    float* out = (float*)d_out;

    __nv_bfloat16 *xT, *wb1, *wbin, *wbo, *wb2, *wxp, *wdt;
    __nv_bfloat16 *t0a, *t0b, *xz, *ub, *dtr, *dtb, *yb, *t2b;
    float *Bm, *Cm, *Hc, *Dc, *hs;
    cudaGetSymbolAddress((void**)&xT,  g_xT);
    cudaGetSymbolAddress((void**)&wb1, g_wb1);
    cudaGetSymbolAddress((void**)&wbin,g_wbin);
    cudaGetSymbolAddress((void**)&wbo, g_wbo);
    cudaGetSymbolAddress((void**)&wb2, g_wb2);
    cudaGetSymbolAddress((void**)&wxp, g_wxp);
    cudaGetSymbolAddress((void**)&wdt, g_wdt);
    cudaGetSymbolAddress((void**)&t0a, g_t0a);
    cudaGetSymbolAddress((void**)&t0b, g_t0b);
    cudaGetSymbolAddress((void**)&xz,  g_xz);
    cudaGetSymbolAddress((void**)&ub,  g_ub);
    cudaGetSymbolAddress((void**)&dtr, g_dtr);
    cudaGetSymbolAddress((void**)&dtb, g_dtb);
    cudaGetSymbolAddress((void**)&Bm,  g_Bm);
    cudaGetSymbolAddress((void**)&Cm,  g_Cm);
    cudaGetSymbolAddress((void**)&Hc,  g_Hc);
    cudaGetSymbolAddress((void**)&Dc,  g_Dc);
    cudaGetSymbolAddress((void**)&hs,  g_hs);
    cudaGetSymbolAddress((void**)&yb,  g_yb);
    cudaGetSymbolAddress((void**)&t2b, g_t2b);

    // fused weight prep (1 launch)
    prep_weights<<<(PREP_TOTAL + 255)/256, 256>>>(
        cv1_w, in_proj_w, out_proj_w, cv2_w, x_proj_w, dt_proj_w,
        wb1, wbin, wbo, wb2, wxp, wdt);
    // x NCHW -> row-major bf16
    xpose<<<dim3(LIMG/32, CDIM/32, BSZ), dim3(32, 8)>>>(x, xT);

    // cv1 -> t0a bf16
    gemm_mma<1><<<dim3(CDIM/128, MROWS/128), 256, SMEM_BYTES>>>(
        xT, wb1, cv1_b, nullptr, t0a, nullptr, nullptr, MROWS, CDIM, CDIM);
    // LN -> t0b bf16
    ln_kernel<<<MROWS, 256>>>(t0a, t0b, ln_g, ln_b);
    // in_proj -> xz bf16
    gemm_mma<1><<<dim3(2*DI/128, MROWS/128), 256, SMEM_BYTES>>>(
        t0b, wbin, nullptr, nullptr, xz, nullptr, nullptr, MROWS, 2*DI, CDIM);
    // conv + silu -> ub bf16
    conv_silu_kernel<<<dim3(LIMG/CLSEG, BSZ), 512>>>(xz, conv_w, conv_b, ub);
    // x_proj GEMM -> dtr(bf16) / Bm / Cm
    gemm_mma<4><<<dim3(1, MROWS/128), 256, SMEM_BYTES>>>(
        ub, wxp, nullptr, nullptr, dtr, Bm, Cm, MROWS, 128, DI);
    // dt_proj GEMM + bias + softplus -> dtb bf16
    gemm_mma<3><<<dim3(DI/128, MROWS/128), 256, SMEM_BYTES>>>(
        dtr, wdt, dt_proj_b, nullptr, dtb, nullptr, nullptr, MROWS, DI, 32);
    // chunked scan
    scan_phase1<<<dim3(NCHUNK, BSZ), 512>>>(dtb, ub, Bm, A_log, Hc, Dc);
    scan_phase2<<<(BSZ*DI)/8, 256>>>(Hc, Dc, A_log, hs);
    scan_phase3<<<dim3(NCHUNK, BSZ), 512>>>(dtb, ub, Bm, Cm, A_log, Dp, xz, hs, yb);
    // out_proj -> t2b bf16
    gemm_mma<1><<<dim3(CDIM/128, MROWS/128), 256, SMEM_BYTES>>>(
        yb, wbo, nullptr, nullptr, t2b, nullptr, nullptr, MROWS, CDIM, DI);
    // cv2 + bias + residual -> out image
    gemm_mma<2><<<dim3(CDIM/128, MROWS/128), 256, SMEM_BYTES>>>(
        t2b, wb2, cv2_b, x, out, nullptr, nullptr, MROWS, CDIM, CDIM);
}